// round 11
// baseline (speedup 1.0000x reference)
#include <cuda_runtime.h>

// GrassmannNN: SITE=8, DIM=16, D=32, B=8192.
// 3 kernels chained with Programmatic Dependent Launch (PDL) so the
// downstream kernel's launch + prolog overlap the upstream's execution:
//   A: 225 blocks — build 28 16x16 layer matrices M + tanh(head) vectors
//   B: 256 pattern-warps — forward all 256 bit patterns -> 32-float table
//   C: 131072 threads — per-row gather (zeros synthesized, not read)

#define NPAT 256

__device__ float g_M[7 * 2 * 2 * 256];          // [l][bit][s][i][k], sign folded
__device__ float g_h[32];                       // tanh(head) per bit
__device__ __align__(16) float g_T[NPAT * 32];  // live sector values only

// ---------------------------------------------------------------------------
// Kernel A: blocks 0..223 -> one (l, ig) slab of body_w each (coalesced 4KB
// load into smem, then 32 threads do the 16-length dots). Block 224 -> head.
// ---------------------------------------------------------------------------
__global__ void __launch_bounds__(256)
precompute_kernel(const float* __restrict__ emb,
                  const float* __restrict__ head_w,
                  const float* __restrict__ body_w) {
    __shared__ __align__(16) float sh[1024];
    const int b = blockIdx.x;
    const int t = threadIdx.x;

    if (b < 224) {
        const int l = b >> 5, ig = b & 31;
        reinterpret_cast<float4*>(sh)[t] =
            reinterpret_cast<const float4*>(body_w + (size_t)(l * 32 + ig) * 1024)[t];
        __syncthreads();
        if (t < 32) {
            const int bit = t >> 4, k = t & 15;
            const int s1 = ig >> 4, i = ig & 15;
            const int s = bit ? (1 - s1) : s1;
            const float* e = emb + ((l + 1) * 2 + bit) * 16;
            float acc = 0.f;
#pragma unroll
            for (int j = 0; j < 16; ++j)
                acc = fmaf(e[j], sh[(bit * 16 + j) * 32 + s * 16 + k], acc);
            if (bit == 1 && s == 0) acc = -acc;
            g_M[(((l * 2 + bit) * 2 + s) * 16 + i) * 16 + k] = acc;
        }
    } else if (t < 32) {
        const int bit = t >> 4, j = t & 15;
        const float* e = emb + bit * 16;                 // embedding[0][bit]
        float acc = 0.f;
#pragma unroll
        for (int k = 0; k < 16; ++k)
            acc = fmaf(e[k], head_w[(bit * 16 + k) * 32 + bit * 16 + j], acc);
        g_h[bit * 16 + j] = tanhf(acc);
    }
    cudaTriggerProgrammaticLaunchCompletion();
}

// ---------------------------------------------------------------------------
// Kernel B: one warp per pattern; lane (s,k) carries state u[s][k].
// Layer matrices double-buffered; PDL-sync before first producer read.
// ---------------------------------------------------------------------------
__global__ void __launch_bounds__(256)
pattern_kernel() {
    const int p = (blockIdx.x * blockDim.x + threadIdx.x) >> 5;
    const int lane = threadIdx.x & 31;
    const int s = lane >> 4, k = lane & 15;
    const int bit0 = p & 1;

    cudaGridDependencySynchronize();            // wait for A's g_M / g_h

    float u = (s == bit0) ? g_h[bit0 * 16 + k] : 0.f;
    float m[16];
    {
        const int bit = (p >> 1) & 1;
        const float* Mp = g_M + ((0 * 2 + bit) * 2 + s) * 256 + k;
#pragma unroll
        for (int i = 0; i < 16; ++i) m[i] = Mp[i * 16];
    }
#pragma unroll
    for (int l = 0; l < 7; ++l) {
        float m2[16];
        if (l < 6) {
            const int bitn = (p >> (l + 2)) & 1;
            const float* Mn = g_M + (((l + 1) * 2 + bitn) * 2 + s) * 256 + k;
#pragma unroll
            for (int i = 0; i < 16; ++i) m2[i] = Mn[i * 16];
        }
        const int bit = (p >> (l + 1)) & 1;
        const int src = (bit ? (1 - s) : s) << 4;
        float acc = 0.f;
#pragma unroll
        for (int i = 0; i < 16; ++i)
            acc = fmaf(__shfl_sync(0xffffffffu, u, src + i), m[i], acc);
        u = tanhf(acc);
#pragma unroll
        for (int i = 0; i < 16; ++i) m[i] = m2[i];
    }

    g_T[p * 32 + s * 16 + k] = u;               // live sector only
    cudaTriggerProgrammaticLaunchCompletion();
}

// ---------------------------------------------------------------------------
// Kernel C: gather — 16 threads per row; structurally-zero halves are
// synthesized, live halves read from the 32 KB table. Prolog (data load,
// pattern index) overlaps kernel B via PDL.
// ---------------------------------------------------------------------------
__global__ void __launch_bounds__(256)
gather_kernel(const int* __restrict__ data, float4* __restrict__ out) {
    const int tid = blockIdx.x * blockDim.x + threadIdx.x;  // 131072
    const int row = tid >> 4;
    const int q   = tid & 15;
    const int4* d4 = reinterpret_cast<const int4*>(data + (size_t)row * 8);
    const int4 a = __ldg(d4);
    const int4 c = __ldg(d4 + 1);
    const int p = a.x | (a.y << 1) | (a.z << 2) | (a.w << 3)
                | (c.x << 4) | (c.y << 5) | (c.z << 6) | (c.w << 7);
    const int sec = q >> 2;                      // 0:s0-live 1,2:zero 3:s1-live

    cudaGridDependencySynchronize();            // wait for B's g_T

    float4 v = make_float4(0.f, 0.f, 0.f, 0.f);
    if (sec == 0)
        v = reinterpret_cast<const float4*>(g_T)[p * 8 + (q & 3)];
    else if (sec == 3)
        v = reinterpret_cast<const float4*>(g_T)[p * 8 + 4 + (q & 3)];
    out[tid] = v;
}

extern "C" void kernel_launch(void* const* d_in, const int* in_sizes, int n_in,
                              void* d_out, int out_size) {
    const int*   data      = (const int*)d_in[0];    // (8192, 8) int32
    const float* embedding = (const float*)d_in[1];  // (8, 2, 16)
    const float* head_w    = (const float*)d_in[2];  // (32, 32)
    const float* body_w    = (const float*)d_in[3];  // (7, 32, 32, 32)
    float* out = (float*)d_out;                      // (8192, 2, 32)

    precompute_kernel<<<225, 256>>>(embedding, head_w, body_w);

    cudaLaunchAttribute attr[1];
    attr[0].id = cudaLaunchAttributeProgrammaticStreamSerialization;
    attr[0].val.programmaticStreamSerializationAllowed = 1;

    {
        cudaLaunchConfig_t cfg = {};
        cfg.gridDim = dim3(32);
        cfg.blockDim = dim3(256);
        cfg.stream = 0;
        cfg.attrs = attr;
        cfg.numAttrs = 1;
        cudaLaunchKernelEx(&cfg, pattern_kernel);
    }
    {
        cudaLaunchConfig_t cfg = {};
        cfg.gridDim = dim3(512);
        cfg.blockDim = dim3(256);
        cfg.stream = 0;
        cfg.attrs = attr;
        cfg.numAttrs = 1;
        cudaLaunchKernelEx(&cfg, gather_kernel, data, (float4*)d_out);
    }
}